// round 5
// baseline (speedup 1.0000x reference)
#include <cuda_runtime.h>
#include <math.h>

#define Bq 4
#define Nq 4096
#define Hq 8
#define Dq 64
#define Mq 64
#define SEG 32
#define BH  (Bq*Hq)
#define P   68          // smem row pitch in floats

// Scratch (fully written each launch)
__device__ float g_KVp[SEG*BH*Dq*Mq];   // partial KV [seg][bh][d][m]
__device__ float g_Ksp[SEG*BH*Dq];      // partial Ksum
__device__ float g_KV[BH*Dq*Mq];
__device__ float g_Ksum[BH*Dq];

__device__ __forceinline__ float fmap(float x) {
    return x > 0.0f ? x + 1.0f : __expf(x);   // elu(x)+1
}
__device__ __forceinline__ float tf32r(float x) {
    float r; asm("cvt.rna.tf32.f32 %0, %1;" : "=f"(r) : "f"(x)); return r;
}
__device__ __forceinline__ void mma_tf32(float4& d,
                                         unsigned a0, unsigned a1, unsigned a2, unsigned a3,
                                         unsigned b0, unsigned b1) {
    asm volatile(
        "mma.sync.aligned.m16n8k8.row.col.f32.tf32.tf32.f32 "
        "{%0,%1,%2,%3}, {%4,%5,%6,%7}, {%8,%9}, {%0,%1,%2,%3};"
        : "+f"(d.x), "+f"(d.y), "+f"(d.z), "+f"(d.w)
        : "r"(a0), "r"(a1), "r"(a2), "r"(a3), "r"(b0), "r"(b1));
}
__device__ __forceinline__ unsigned fau(float x) { return __float_as_uint(x); }

// ============ pass1: KV_partial[seg][bh] = fmap(K)^T V over this seg's 128 rows ============
// grid (SEG, H, B) = 1024 blocks, 256 thr (8 warps). Output tile 64(d) x 64(m).
// Warp w: d-strip = w%4 (16 rows), m j-tiles = 4*(w/4)..+3.
__global__ void __launch_bounds__(256) pass1_kernel(const float* __restrict__ Kp,
                                                    const float* __restrict__ Vp) {
    __shared__ float Ksm[64][P];   // fmapped+tf32 K tile, [n][d]
    __shared__ float Vsm[64][P];   // tf32 V tile,         [n][m]

    const int b = blockIdx.z, h = blockIdx.y, seg = blockIdx.x;
    const int bh = b * Hq + h;
    const int tid = threadIdx.x;
    const int w = tid >> 5, lane = tid & 31;
    const int gid = lane >> 2, tig = lane & 3;
    const int mt = w & 3;
    const int jt0 = (w >> 2) * 4;

    float4 acc[4];
    #pragma unroll
    for (int j = 0; j < 4; j++) acc[j] = make_float4(0.f, 0.f, 0.f, 0.f);
    float ksum = 0.0f;  // valid for tid < 64 (d = tid)

    for (int c = 0; c < 2; c++) {
        const int n0 = seg * (Nq / SEG) + c * 64;
        __syncthreads();
        #pragma unroll
        for (int it = 0; it < 4; it++) {
            const int idx = it * 256 + tid;
            const int n = idx >> 4, c4 = idx & 15;
            const size_t base = ((size_t)(b * Nq + n0 + n) * Hq + h);
            float4 k4 = *(const float4*)(Kp + base * Dq + c4 * 4);
            k4.x = tf32r(fmap(k4.x)); k4.y = tf32r(fmap(k4.y));
            k4.z = tf32r(fmap(k4.z)); k4.w = tf32r(fmap(k4.w));
            *(float4*)&Ksm[n][c4 * 4] = k4;
            float4 v4 = *(const float4*)(Vp + base * Mq + c4 * 4);
            v4.x = tf32r(v4.x); v4.y = tf32r(v4.y);
            v4.z = tf32r(v4.z); v4.w = tf32r(v4.w);
            *(float4*)&Vsm[n][c4 * 4] = v4;
        }
        __syncthreads();

        // Ksum partial (threads 0..63, d = tid)
        if (tid < 64) {
            float s = 0.0f;
            #pragma unroll 8
            for (int n = 0; n < 64; n++) s += Ksm[n][tid];
            ksum += s;
        }

        // MMA mainloop: contraction over 64 staged rows (8 k-steps of 8)
        #pragma unroll
        for (int ks = 0; ks < 8; ks++) {
            const int k0 = ks * 8;
            // A = K'^T: A[d][n] gathered from Ksm[n][d] (index swap, no transpose)
            const unsigned a0 = fau(Ksm[k0 + tig    ][16 * mt + gid    ]);
            const unsigned a1 = fau(Ksm[k0 + tig    ][16 * mt + gid + 8]);
            const unsigned a2 = fau(Ksm[k0 + tig + 4][16 * mt + gid    ]);
            const unsigned a3 = fau(Ksm[k0 + tig + 4][16 * mt + gid + 8]);
            #pragma unroll
            for (int j = 0; j < 4; j++) {
                const unsigned b0 = fau(Vsm[k0 + tig    ][(jt0 + j) * 8 + gid]);
                const unsigned b1 = fau(Vsm[k0 + tig + 4][(jt0 + j) * 8 + gid]);
                mma_tf32(acc[j], a0, a1, a2, a3, b0, b1);
            }
        }
    }

    // epilogue: write partial KV (block exclusively owns [seg][bh])
    float* kv = g_KVp + ((size_t)seg * BH + bh) * Dq * Mq;
    const int d = 16 * mt + gid;
    #pragma unroll
    for (int j = 0; j < 4; j++) {
        const int m = (jt0 + j) * 8 + 2 * tig;
        *(float2*)(kv + (size_t)d * Mq + m)       = make_float2(acc[j].x, acc[j].y);
        *(float2*)(kv + (size_t)(d + 8) * Mq + m) = make_float2(acc[j].z, acc[j].w);
    }
    if (tid < 64) g_Ksp[((size_t)seg * BH + bh) * Dq + tid] = ksum;
}

// ============ reduce: sum SEG partials ============
__global__ void __launch_bounds__(256) reduce_kernel() {
    const int i = blockIdx.x * 256 + threadIdx.x;
    if (i < BH * Dq * Mq) {
        float s = 0.0f;
        #pragma unroll
        for (int sg = 0; sg < SEG; sg++) s += g_KVp[(size_t)sg * BH * Dq * Mq + i];
        g_KV[i] = s;
    }
    if (i < BH * Dq) {
        float s = 0.0f;
        #pragma unroll
        for (int sg = 0; sg < SEG; sg++) s += g_Ksp[sg * BH * Dq + i];
        g_Ksum[i] = s;
    }
}

// ============ pass2: out = Z * fmap(Q) @ KV ============
// grid (64, H, B) = 2048 blocks, 256 thr (8 warps). Tile: 64 n-rows x 64 m.
// Warp w: n-strip = w%4 (16 rows), m j-tiles = 4*(w/4)..+3.
__global__ void __launch_bounds__(256) pass2_kernel(const float* __restrict__ Qp,
                                                    float* __restrict__ Op) {
    __shared__ float Qsm[64][P];    // fmapped+tf32 Q tile [n][d]
    __shared__ float KVsm[64][P];   // tf32 KV tile        [d][m]
    __shared__ float Zs[64];
    __shared__ float Kss[64];

    const int b = blockIdx.z, h = blockIdx.y;
    const int bh = b * Hq + h;
    const int n0 = blockIdx.x * 64;
    const int tid = threadIdx.x;
    const int w = tid >> 5, lane = tid & 31;
    const int gid = lane >> 2, tig = lane & 3;
    const int mt = w & 3;
    const int jt0 = (w >> 2) * 4;

    // stage KV (tf32-rounded) and Q' (fmap + tf32)
    #pragma unroll
    for (int it = 0; it < 4; it++) {
        const int idx = it * 256 + tid;
        const int r = idx >> 4, c4 = idx & 15;
        float4 t = *(const float4*)(g_KV + (size_t)bh * Dq * Mq + r * Mq + c4 * 4);
        t.x = tf32r(t.x); t.y = tf32r(t.y); t.z = tf32r(t.z); t.w = tf32r(t.w);
        *(float4*)&KVsm[r][c4 * 4] = t;

        float4 q4 = *(const float4*)(Qp + ((size_t)(b * Nq + n0 + r) * Hq + h) * Dq + c4 * 4);
        q4.x = tf32r(fmap(q4.x)); q4.y = tf32r(fmap(q4.y));
        q4.z = tf32r(fmap(q4.z)); q4.w = tf32r(fmap(q4.w));
        *(float4*)&Qsm[r][c4 * 4] = q4;
    }
    if (tid < 64) Kss[tid] = g_Ksum[bh * Dq + tid];
    __syncthreads();

    // Z per row
    if (tid < 64) {
        float s = 0.0f;
        #pragma unroll 8
        for (int d = 0; d < Dq; d++) s += Qsm[tid][d] * Kss[d];
        Zs[tid] = 1.0f / (s + 1e-6f);
    }
    __syncthreads();

    float4 acc[4];
    #pragma unroll
    for (int j = 0; j < 4; j++) acc[j] = make_float4(0.f, 0.f, 0.f, 0.f);

    #pragma unroll
    for (int ks = 0; ks < 8; ks++) {
        const int k0 = ks * 8;
        const unsigned a0 = fau(Qsm[16 * mt + gid    ][k0 + tig    ]);
        const unsigned a1 = fau(Qsm[16 * mt + gid + 8][k0 + tig    ]);
        const unsigned a2 = fau(Qsm[16 * mt + gid    ][k0 + tig + 4]);
        const unsigned a3 = fau(Qsm[16 * mt + gid + 8][k0 + tig + 4]);
        #pragma unroll
        for (int j = 0; j < 4; j++) {
            const unsigned b0 = fau(KVsm[k0 + tig    ][(jt0 + j) * 8 + gid]);
            const unsigned b1 = fau(KVsm[k0 + tig + 4][(jt0 + j) * 8 + gid]);
            mma_tf32(acc[j], a0, a1, a2, a3, b0, b1);
        }
    }

    // epilogue: scale by Z, store
    const int row = 16 * mt + gid;
    const float z0 = Zs[row], z1 = Zs[row + 8];
    float* op0 = Op + ((size_t)(b * Nq + n0 + row) * Hq + h) * Mq;
    float* op1 = op0 + (size_t)8 * Hq * Mq;
    #pragma unroll
    for (int j = 0; j < 4; j++) {
        const int m = (jt0 + j) * 8 + 2 * tig;
        *(float2*)(op0 + m) = make_float2(acc[j].x * z0, acc[j].y * z0);
        *(float2*)(op1 + m) = make_float2(acc[j].z * z1, acc[j].w * z1);
    }
}

extern "C" void kernel_launch(void* const* d_in, const int* in_sizes, int n_in,
                              void* d_out, int out_size) {
    const float* Q = (const float*)d_in[0];
    const float* K = (const float*)d_in[1];
    const float* V = (const float*)d_in[2];
    float* out = (float*)d_out;

    pass1_kernel<<<dim3(SEG, Hq, Bq), 256>>>(K, V);
    reduce_kernel<<<512, 256>>>();
    pass2_kernel<<<dim3(64, Hq, Bq), 256>>>(Q, out);
}

// round 6
// speedup vs baseline: 1.3146x; 1.3146x over previous
#include <cuda_runtime.h>
#include <cuda_fp16.h>
#include <math.h>

#define Bq 4
#define Nq 4096
#define Hq 8
#define Dq 64
#define Mq 64
#define SEG 32
#define BH  (Bq*Hq)
#define P2  72          // smem row pitch in halves (36 words -> conflict-free)

// Scratch (fully written each launch)
__device__ float g_KVp[SEG*BH*Dq*Mq];   // partial KV [seg][bh][d][m]
__device__ float g_Ksp[SEG*BH*Dq];      // partial Ksum
__device__ float g_KV[BH*Dq*Mq];
__device__ float g_Ksum[BH*Dq];

__device__ __forceinline__ float fmap(float x) {
    return x > 0.0f ? x + 1.0f : __expf(x);   // elu(x)+1
}
__device__ __forceinline__ unsigned pack_h2(float lo, float hi) {
    __half2 h = __floats2half2_rn(lo, hi);
    return *reinterpret_cast<unsigned*>(&h);
}
__device__ __forceinline__ float2 unpack_h2(unsigned u) {
    __half2 h = *reinterpret_cast<__half2*>(&u);
    return __half22float2(h);
}
__device__ __forceinline__ void mma_fp16(float4& d,
                                         unsigned a0, unsigned a1, unsigned a2, unsigned a3,
                                         unsigned b0, unsigned b1) {
    asm volatile(
        "mma.sync.aligned.m16n8k16.row.col.f32.f16.f16.f32 "
        "{%0,%1,%2,%3}, {%4,%5,%6,%7}, {%8,%9}, {%0,%1,%2,%3};"
        : "+f"(d.x), "+f"(d.y), "+f"(d.z), "+f"(d.w)
        : "r"(a0), "r"(a1), "r"(a2), "r"(a3), "r"(b0), "r"(b1));
}

// ============ pass1: KV_partial[seg][bh] = fmap(K)^T V over this seg's 128 rows ============
// grid (SEG, H, B) = 1024 blocks, 128 thr (4 warps). Output tile 64(d) x 64(m).
// Warp w: d-strips {2(w&1), 2(w&1)+1} (32 d-rows), m j-tiles 4*(w>>1)..+3 (32 m).
// Smem: K', V stored TRANSPOSED as half2: Kt[d][n], Vt[m][n].
__global__ void __launch_bounds__(128) pass1_kernel(const float* __restrict__ Kp,
                                                    const float* __restrict__ Vp) {
    __shared__ unsigned short Kt[64][P2];
    __shared__ unsigned short Vt[64][P2];

    const int b = blockIdx.z, h = blockIdx.y, seg = blockIdx.x;
    const int bh = b * Hq + h;
    const int tid = threadIdx.x;
    const int w = tid >> 5, lane = tid & 31;
    const int gid = lane >> 2, tig = lane & 3;
    const int s0 = (w & 1) * 2;      // first d-strip (of 2)
    const int jt0 = (w >> 1) * 4;    // first m j-tile (of 4)

    float4 acc[2][4];
    #pragma unroll
    for (int i = 0; i < 2; i++)
        #pragma unroll
        for (int j = 0; j < 4; j++) acc[i][j] = make_float4(0.f, 0.f, 0.f, 0.f);
    float ksum = 0.0f;               // valid for tid < 64 (d = tid)

    for (int c = 0; c < 2; c++) {
        const int n0 = seg * (Nq / SEG) + c * 64;
        __syncthreads();
        // stage transposed: 512 jobs = 32 row-pairs x 16 col-chunks
        #pragma unroll
        for (int it = 0; it < 4; it++) {
            const int job = it * 128 + tid;
            const int r2 = job & 31, c4 = job >> 5;
            const size_t base = ((size_t)(b * Nq + n0 + 2 * r2) * Hq + h);
            float4 ka = *(const float4*)(Kp + base * Dq + c4 * 4);
            float4 kb = *(const float4*)(Kp + (base + Hq) * Dq + c4 * 4);
            *(unsigned*)&Kt[c4 * 4 + 0][2 * r2] = pack_h2(fmap(ka.x), fmap(kb.x));
            *(unsigned*)&Kt[c4 * 4 + 1][2 * r2] = pack_h2(fmap(ka.y), fmap(kb.y));
            *(unsigned*)&Kt[c4 * 4 + 2][2 * r2] = pack_h2(fmap(ka.z), fmap(kb.z));
            *(unsigned*)&Kt[c4 * 4 + 3][2 * r2] = pack_h2(fmap(ka.w), fmap(kb.w));
            float4 va = *(const float4*)(Vp + base * Mq + c4 * 4);
            float4 vb = *(const float4*)(Vp + (base + Hq) * Mq + c4 * 4);
            *(unsigned*)&Vt[c4 * 4 + 0][2 * r2] = pack_h2(va.x, vb.x);
            *(unsigned*)&Vt[c4 * 4 + 1][2 * r2] = pack_h2(va.y, vb.y);
            *(unsigned*)&Vt[c4 * 4 + 2][2 * r2] = pack_h2(va.z, vb.z);
            *(unsigned*)&Vt[c4 * 4 + 3][2 * r2] = pack_h2(va.w, vb.w);
        }
        __syncthreads();

        // Ksum partial (threads 0..63, d = tid): row-contiguous half2 reads
        if (tid < 64) {
            float s = 0.0f;
            #pragma unroll
            for (int i = 0; i < 32; i++) {
                float2 f = unpack_h2(*(const unsigned*)&Kt[tid][2 * i]);
                s += f.x + f.y;
            }
            ksum += s;
        }

        // MMA mainloop: 4 k-steps of 16 over the 64 staged rows
        #pragma unroll
        for (int ks = 0; ks < 4; ks++) {
            const int k0 = ks * 16;
            unsigned a[2][4];
            #pragma unroll
            for (int si = 0; si < 2; si++) {
                const int d = 16 * (s0 + si);
                a[si][0] = *(const unsigned*)&Kt[d + gid    ][k0 + 2 * tig];
                a[si][1] = *(const unsigned*)&Kt[d + gid + 8][k0 + 2 * tig];
                a[si][2] = *(const unsigned*)&Kt[d + gid    ][k0 + 2 * tig + 8];
                a[si][3] = *(const unsigned*)&Kt[d + gid + 8][k0 + 2 * tig + 8];
            }
            #pragma unroll
            for (int j = 0; j < 4; j++) {
                const int m = 8 * (jt0 + j) + gid;
                const unsigned b0 = *(const unsigned*)&Vt[m][k0 + 2 * tig];
                const unsigned b1 = *(const unsigned*)&Vt[m][k0 + 2 * tig + 8];
                mma_fp16(acc[0][j], a[0][0], a[0][1], a[0][2], a[0][3], b0, b1);
                mma_fp16(acc[1][j], a[1][0], a[1][1], a[1][2], a[1][3], b0, b1);
            }
        }
    }

    // epilogue: write partial KV (block exclusively owns [seg][bh])
    float* kv = g_KVp + ((size_t)seg * BH + bh) * Dq * Mq;
    #pragma unroll
    for (int si = 0; si < 2; si++) {
        const int d = 16 * (s0 + si) + gid;
        #pragma unroll
        for (int j = 0; j < 4; j++) {
            const int m = 8 * (jt0 + j) + 2 * tig;
            *(float2*)(kv + (size_t)d * Mq + m)       = make_float2(acc[si][j].x, acc[si][j].y);
            *(float2*)(kv + (size_t)(d + 8) * Mq + m) = make_float2(acc[si][j].z, acc[si][j].w);
        }
    }
    if (tid < 64) g_Ksp[((size_t)seg * BH + bh) * Dq + tid] = ksum;
}

// ============ reduce: sum SEG partials ============
__global__ void __launch_bounds__(256) reduce_kernel() {
    const int i = blockIdx.x * 256 + threadIdx.x;
    if (i < BH * Dq * Mq) {
        float s = 0.0f;
        #pragma unroll
        for (int sg = 0; sg < SEG; sg++) s += g_KVp[(size_t)sg * BH * Dq * Mq + i];
        g_KV[i] = s;
    }
    if (i < BH * Dq) {
        float s = 0.0f;
        #pragma unroll
        for (int sg = 0; sg < SEG; sg++) s += g_Ksp[sg * BH * Dq + i];
        g_Ksum[i] = s;
    }
}

// ============ pass2: out = Z * fmap(Q) @ KV ============
// grid (64, H, B) = 2048 blocks, 128 thr (4 warps). Tile: 64 n-rows x 64 m.
// Warp w: n-strips {2(w&1), 2(w&1)+1}, m j-tiles 4*(w>>1)..+3.
// Smem: Q' natural [n][d] (A row-major needs d-adjacent); KV transposed [m][d].
__global__ void __launch_bounds__(128) pass2_kernel(const float* __restrict__ Qp,
                                                    float* __restrict__ Op) {
    __shared__ unsigned short Qs[64][P2];    // [n][d]
    __shared__ unsigned short KVt[64][P2];   // [m][d]
    __shared__ float Zs[64];
    __shared__ float Kss[64];

    const int b = blockIdx.z, h = blockIdx.y;
    const int bh = b * Hq + h;
    const int n0 = blockIdx.x * 64;
    const int tid = threadIdx.x;
    const int w = tid >> 5, lane = tid & 31;
    const int gid = lane >> 2, tig = lane & 3;
    const int s0 = (w & 1) * 2;
    const int jt0 = (w >> 1) * 4;

    // stage KV transposed: 512 jobs = 32 d-pairs x 16 m-chunks
    const float* kvg = g_KV + (size_t)bh * Dq * Mq;
    #pragma unroll
    for (int it = 0; it < 4; it++) {
        const int job = it * 128 + tid;
        const int dp = job & 31, c4 = job >> 5;
        float4 a = *(const float4*)(kvg + (2 * dp) * Mq + c4 * 4);
        float4 bb = *(const float4*)(kvg + (2 * dp + 1) * Mq + c4 * 4);
        *(unsigned*)&KVt[c4 * 4 + 0][2 * dp] = pack_h2(a.x, bb.x);
        *(unsigned*)&KVt[c4 * 4 + 1][2 * dp] = pack_h2(a.y, bb.y);
        *(unsigned*)&KVt[c4 * 4 + 2][2 * dp] = pack_h2(a.z, bb.z);
        *(unsigned*)&KVt[c4 * 4 + 3][2 * dp] = pack_h2(a.w, bb.w);
    }
    if (tid < 64) Kss[tid] = g_Ksum[bh * Dq + tid];

    // stage Q' natural: 1024 jobs = 64 rows x 16 chunks
    #pragma unroll
    for (int it = 0; it < 8; it++) {
        const int job = it * 128 + tid;
        const int n = job >> 4, c4 = job & 15;
        float4 q = *(const float4*)(Qp + ((size_t)(b * Nq + n0 + n) * Hq + h) * Dq + c4 * 4);
        uint2 u;
        u.x = pack_h2(fmap(q.x), fmap(q.y));
        u.y = pack_h2(fmap(q.z), fmap(q.w));
        *(uint2*)&Qs[n][c4 * 4] = u;
    }
    __syncthreads();

    // Z per row
    if (tid < 64) {
        float s = 0.0f;
        #pragma unroll
        for (int i = 0; i < 32; i++) {
            float2 q2 = unpack_h2(*(const unsigned*)&Qs[tid][2 * i]);
            s += q2.x * Kss[2 * i] + q2.y * Kss[2 * i + 1];
        }
        Zs[tid] = 1.0f / (s + 1e-6f);
    }
    __syncthreads();

    float4 acc[2][4];
    #pragma unroll
    for (int i = 0; i < 2; i++)
        #pragma unroll
        for (int j = 0; j < 4; j++) acc[i][j] = make_float4(0.f, 0.f, 0.f, 0.f);

    #pragma unroll
    for (int ks = 0; ks < 4; ks++) {
        const int k0 = ks * 16;
        unsigned a[2][4];
        #pragma unroll
        for (int si = 0; si < 2; si++) {
            const int n = 16 * (s0 + si);
            a[si][0] = *(const unsigned*)&Qs[n + gid    ][k0 + 2 * tig];
            a[si][1] = *(const unsigned*)&Qs[n + gid + 8][k0 + 2 * tig];
            a[si][2] = *(const unsigned*)&Qs[n + gid    ][k0 + 2 * tig + 8];
            a[si][3] = *(const unsigned*)&Qs[n + gid + 8][k0 + 2 * tig + 8];
        }
        #pragma unroll
        for (int j = 0; j < 4; j++) {
            const int m = 8 * (jt0 + j) + gid;
            const unsigned b0 = *(const unsigned*)&KVt[m][k0 + 2 * tig];
            const unsigned b1 = *(const unsigned*)&KVt[m][k0 + 2 * tig + 8];
            mma_fp16(acc[0][j], a[0][0], a[0][1], a[0][2], a[0][3], b0, b1);
            mma_fp16(acc[1][j], a[1][0], a[1][1], a[1][2], a[1][3], b0, b1);
        }
    }

    // epilogue: scale by Z, store
    #pragma unroll
    for (int si = 0; si < 2; si++) {
        const int row = 16 * (s0 + si) + gid;
        const float z0 = Zs[row], z1 = Zs[row + 8];
        float* op0 = Op + ((size_t)(b * Nq + n0 + row) * Hq + h) * Mq;
        float* op1 = op0 + (size_t)8 * Hq * Mq;
        #pragma unroll
        for (int j = 0; j < 4; j++) {
            const int m = 8 * (jt0 + j) + 2 * tig;
            *(float2*)(op0 + m) = make_float2(acc[si][j].x * z0, acc[si][j].y * z0);
            *(float2*)(op1 + m) = make_float2(acc[si][j].z * z1, acc[si][j].w * z1);
        }
    }
}

extern "C" void kernel_launch(void* const* d_in, const int* in_sizes, int n_in,
                              void* d_out, int out_size) {
    const float* Q = (const float*)d_in[0];
    const float* K = (const float*)d_in[1];
    const float* V = (const float*)d_in[2];
    float* out = (float*)d_out;

    pass1_kernel<<<dim3(SEG, Hq, Bq), 128>>>(K, V);
    reduce_kernel<<<512, 256>>>();
    pass2_kernel<<<dim3(64, Hq, Bq), 128>>>(Q, out);
}

// round 7
// speedup vs baseline: 1.4836x; 1.1286x over previous
#include <cuda_runtime.h>
#include <cuda_fp16.h>
#include <math.h>

#define Bq 4
#define Nq 4096
#define Hq 8
#define Dq 64
#define Mq 64
#define SEG 32
#define BH  (Bq*Hq)
#define P2  72          // smem row pitch in halves (144B: 16B-aligned, ldmatrix conflict-free)

// Scratch (fully written each launch)
__device__ float g_KVp[SEG*BH*Dq*Mq];   // partial KV [seg][bh][d][m]
__device__ float g_Ksp[SEG*BH*Dq];      // partial Ksum
__device__ float g_KV[BH*Dq*Mq];
__device__ float g_Ksum[BH*Dq];

__device__ __forceinline__ float fmap(float x) {
    return x > 0.0f ? x + 1.0f : __expf(x);   // elu(x)+1
}
__device__ __forceinline__ unsigned pack_h2(float lo, float hi) {
    __half2 h = __floats2half2_rn(lo, hi);
    return *reinterpret_cast<unsigned*>(&h);
}
__device__ __forceinline__ void mma_fp16(float4& d,
                                         unsigned a0, unsigned a1, unsigned a2, unsigned a3,
                                         unsigned b0, unsigned b1) {
    asm volatile(
        "mma.sync.aligned.m16n8k16.row.col.f32.f16.f16.f32 "
        "{%0,%1,%2,%3}, {%4,%5,%6,%7}, {%8,%9}, {%0,%1,%2,%3};"
        : "+f"(d.x), "+f"(d.y), "+f"(d.z), "+f"(d.w)
        : "r"(a0), "r"(a1), "r"(a2), "r"(a3), "r"(b0), "r"(b1));
}
__device__ __forceinline__ void ldm_x4t(unsigned& r0, unsigned& r1, unsigned& r2, unsigned& r3,
                                        unsigned addr) {
    asm volatile("ldmatrix.sync.aligned.m8n8.x4.trans.shared.b16 {%0,%1,%2,%3}, [%4];"
        : "=r"(r0), "=r"(r1), "=r"(r2), "=r"(r3) : "r"(addr));
}
__device__ __forceinline__ void ldm_x4(unsigned& r0, unsigned& r1, unsigned& r2, unsigned& r3,
                                       unsigned addr) {
    asm volatile("ldmatrix.sync.aligned.m8n8.x4.shared.b16 {%0,%1,%2,%3}, [%4];"
        : "=r"(r0), "=r"(r1), "=r"(r2), "=r"(r3) : "r"(addr));
}
__device__ __forceinline__ void ldm_x2t(unsigned& r0, unsigned& r1, unsigned addr) {
    asm volatile("ldmatrix.sync.aligned.m8n8.x2.trans.shared.b16 {%0,%1}, [%2];"
        : "=r"(r0), "=r"(r1) : "r"(addr));
}

// ============ pass1: KV_partial[seg][bh] = fmap(K)^T V over this seg's 128 rows ============
// grid (SEG, H, B) = 1024 blocks, 128 thr (4 warps). Output tile 64(d) x 64(m).
// Warp w: d-strips {2(w&1), 2(w&1)+1} (32 d), m j-tiles 4*(w>>1)..+3 (32 m).
// Smem: natural layout Ksm[n][d], Vsm[n][m]; transpose happens in ldmatrix.trans.
__global__ void __launch_bounds__(128) pass1_kernel(const float* __restrict__ Kp,
                                                    const float* __restrict__ Vp) {
    __shared__ __align__(16) __half Ksm[64][P2];
    __shared__ __align__(16) __half Vsm[64][P2];

    const int b = blockIdx.z, h = blockIdx.y, seg = blockIdx.x;
    const int bh = b * Hq + h;
    const int tid = threadIdx.x;
    const int w = tid >> 5, lane = tid & 31;
    const int gid = lane >> 2, tig = lane & 3;
    const int s0 = (w & 1) * 2;      // first d-strip (of 2)
    const int jt0 = (w >> 1) * 4;    // first m j-tile (of 4)

    const unsigned Kbase = (unsigned)__cvta_generic_to_shared(&Ksm[0][0]);
    const unsigned Vbase = (unsigned)__cvta_generic_to_shared(&Vsm[0][0]);
    // ldmatrix lane-address components
    const int g = lane >> 3, r = lane & 7;
    // A (trans, x4): row = k0 + (g>=2?8:0) + r ; col = d0 + (g&1?8:0)
    const int arow_off = ((g >> 1) ? 8 : 0) + r;
    const int acol_off = (g & 1) ? 8 : 0;
    // B (trans, x2): row = k0 + (g&1?8:0) + r ; col = m0   (lanes 16-31 ignored; keep valid)
    const int brow_off = ((g & 1) ? 8 : 0) + r;

    float4 acc[2][4];
    #pragma unroll
    for (int i = 0; i < 2; i++)
        #pragma unroll
        for (int j = 0; j < 4; j++) acc[i][j] = make_float4(0.f, 0.f, 0.f, 0.f);
    float ksum = 0.0f;               // valid for tid < 64 (d = tid)

    for (int c = 0; c < 2; c++) {
        const int n0 = seg * (Nq / SEG) + c * 64;
        __syncthreads();
        // coalesced staging: jobs = (n, c4), c4 in low bits
        #pragma unroll
        for (int it = 0; it < 8; it++) {
            const int job = it * 128 + tid;
            const int n = job >> 4, c4 = job & 15;
            const size_t base = ((size_t)(b * Nq + n0 + n) * Hq + h);
            float4 k4 = *(const float4*)(Kp + base * Dq + c4 * 4);
            uint2 ku;
            ku.x = pack_h2(fmap(k4.x), fmap(k4.y));
            ku.y = pack_h2(fmap(k4.z), fmap(k4.w));
            *(uint2*)&Ksm[n][c4 * 4] = ku;
            float4 v4 = *(const float4*)(Vp + base * Mq + c4 * 4);
            uint2 vu;
            vu.x = pack_h2(v4.x, v4.y);
            vu.y = pack_h2(v4.z, v4.w);
            *(uint2*)&Vsm[n][c4 * 4] = vu;
        }
        __syncthreads();

        // Ksum partial (threads 0..63, d = tid)
        if (tid < 64) {
            float s = 0.0f;
            #pragma unroll
            for (int n = 0; n < 64; n++) s += __half2float(Ksm[n][tid]);
            ksum += s;
        }

        // MMA mainloop: 4 k-steps of 16 over the 64 staged rows
        #pragma unroll
        for (int ks = 0; ks < 4; ks++) {
            const int k0 = ks * 16;
            unsigned a[2][4];
            #pragma unroll
            for (int si = 0; si < 2; si++) {
                const int d0 = 16 * (s0 + si);
                const unsigned addr = Kbase +
                    ((unsigned)((k0 + arow_off) * P2 + d0 + acol_off)) * 2u;
                ldm_x4t(a[si][0], a[si][1], a[si][2], a[si][3], addr);
            }
            #pragma unroll
            for (int j = 0; j < 4; j++) {
                const int m0 = 8 * (jt0 + j);
                unsigned b0, b1;
                const unsigned baddr = Vbase +
                    ((unsigned)((k0 + brow_off) * P2 + m0)) * 2u;
                ldm_x2t(b0, b1, baddr);
                mma_fp16(acc[0][j], a[0][0], a[0][1], a[0][2], a[0][3], b0, b1);
                mma_fp16(acc[1][j], a[1][0], a[1][1], a[1][2], a[1][3], b0, b1);
            }
        }
    }

    // epilogue: write partial KV (block exclusively owns [seg][bh])
    float* kv = g_KVp + ((size_t)seg * BH + bh) * Dq * Mq;
    #pragma unroll
    for (int si = 0; si < 2; si++) {
        const int d = 16 * (s0 + si) + gid;
        #pragma unroll
        for (int j = 0; j < 4; j++) {
            const int m = 8 * (jt0 + j) + 2 * tig;
            *(float2*)(kv + (size_t)d * Mq + m)       = make_float2(acc[si][j].x, acc[si][j].y);
            *(float2*)(kv + (size_t)(d + 8) * Mq + m) = make_float2(acc[si][j].z, acc[si][j].w);
        }
    }
    if (tid < 64) g_Ksp[((size_t)seg * BH + bh) * Dq + tid] = ksum;
}

// ============ reduce: sum SEG partials ============
__global__ void __launch_bounds__(256) reduce_kernel() {
    const int i = blockIdx.x * 256 + threadIdx.x;
    if (i < BH * Dq * Mq) {
        float s = 0.0f;
        #pragma unroll
        for (int sg = 0; sg < SEG; sg++) s += g_KVp[(size_t)sg * BH * Dq * Mq + i];
        g_KV[i] = s;
    }
    if (i < BH * Dq) {
        float s = 0.0f;
        #pragma unroll
        for (int sg = 0; sg < SEG; sg++) s += g_Ksp[sg * BH * Dq + i];
        g_Ksum[i] = s;
    }
}

// ============ pass2: out = Z * fmap(Q) @ KV ============
// grid (64, H, B) = 2048 blocks, 128 thr (4 warps). Tile: 64 n-rows x 64 m.
// Warp w: n-strips {2(w&1), 2(w&1)+1}, m j-tiles 4*(w>>1)..+3.
// Smem natural: Qsm[n][d] (A row-major, non-trans ldmatrix), KVsm[d][m] (B via trans).
__global__ void __launch_bounds__(128) pass2_kernel(const float* __restrict__ Qp,
                                                    float* __restrict__ Op) {
    __shared__ __align__(16) __half Qsm[64][P2];
    __shared__ __align__(16) __half KVsm[64][P2];
    __shared__ float Zs[64];
    __shared__ float Kss[64];

    const int b = blockIdx.z, h = blockIdx.y;
    const int bh = b * Hq + h;
    const int n0 = blockIdx.x * 64;
    const int tid = threadIdx.x;
    const int w = tid >> 5, lane = tid & 31;
    const int gid = lane >> 2, tig = lane & 3;
    const int s0 = (w & 1) * 2;
    const int jt0 = (w >> 1) * 4;

    const unsigned Qbase  = (unsigned)__cvta_generic_to_shared(&Qsm[0][0]);
    const unsigned KVbase = (unsigned)__cvta_generic_to_shared(&KVsm[0][0]);
    const int g = lane >> 3, r = lane & 7;
    // A (non-trans, x4): row = nrow0 + (g&1?8:0) + r ; col = k0 + (g>=2?8:0)
    const int arow_off = ((g & 1) ? 8 : 0) + r;
    const int acol_off = (g >> 1) ? 8 : 0;
    // B (trans, x2): row = k0 + (g&1?8:0) + r ; col = m0
    const int brow_off = ((g & 1) ? 8 : 0) + r;

    // coalesced staging: KV [d][m] and Q' [n][d]
    const float* kvg = g_KV + (size_t)bh * Dq * Mq;
    #pragma unroll
    for (int it = 0; it < 8; it++) {
        const int job = it * 128 + tid;
        const int rr = job >> 4, c4 = job & 15;
        float4 t = *(const float4*)(kvg + (size_t)rr * Mq + c4 * 4);
        uint2 tu;
        tu.x = pack_h2(t.x, t.y);
        tu.y = pack_h2(t.z, t.w);
        *(uint2*)&KVsm[rr][c4 * 4] = tu;

        float4 q = *(const float4*)(Qp + ((size_t)(b * Nq + n0 + rr) * Hq + h) * Dq + c4 * 4);
        uint2 qu;
        qu.x = pack_h2(fmap(q.x), fmap(q.y));
        qu.y = pack_h2(fmap(q.z), fmap(q.w));
        *(uint2*)&Qsm[rr][c4 * 4] = qu;
    }
    if (tid < 64) Kss[tid] = g_Ksum[bh * Dq + tid];
    __syncthreads();

    // Z per row
    if (tid < 64) {
        float s = 0.0f;
        #pragma unroll
        for (int d = 0; d < Dq; d++) s += __half2float(Qsm[tid][d]) * Kss[d];
        Zs[tid] = 1.0f / (s + 1e-6f);
    }
    __syncthreads();

    float4 acc[2][4];
    #pragma unroll
    for (int i = 0; i < 2; i++)
        #pragma unroll
        for (int j = 0; j < 4; j++) acc[i][j] = make_float4(0.f, 0.f, 0.f, 0.f);

    #pragma unroll
    for (int ks = 0; ks < 4; ks++) {
        const int k0 = ks * 16;
        unsigned a[2][4];
        #pragma unroll
        for (int si = 0; si < 2; si++) {
            const int nr0 = 16 * (s0 + si);
            const unsigned addr = Qbase +
                ((unsigned)((nr0 + arow_off) * P2 + k0 + acol_off)) * 2u;
            ldm_x4(a[si][0], a[si][1], a[si][2], a[si][3], addr);
        }
        #pragma unroll
        for (int j = 0; j < 4; j++) {
            const int m0 = 8 * (jt0 + j);
            unsigned b0, b1;
            const unsigned baddr = KVbase +
                ((unsigned)((k0 + brow_off) * P2 + m0)) * 2u;
            ldm_x2t(b0, b1, baddr);
            mma_fp16(acc[0][j], a[0][0], a[0][1], a[0][2], a[0][3], b0, b1);
            mma_fp16(acc[1][j], a[1][0], a[1][1], a[1][2], a[1][3], b0, b1);
        }
    }

    // epilogue: scale by Z, store
    #pragma unroll
    for (int si = 0; si < 2; si++) {
        const int row = 16 * (s0 + si) + gid;
        const float z0 = Zs[row], z1 = Zs[row + 8];
        float* op0 = Op + ((size_t)(b * Nq + n0 + row) * Hq + h) * Mq;
        float* op1 = op0 + (size_t)8 * Hq * Mq;
        #pragma unroll
        for (int j = 0; j < 4; j++) {
            const int m = 8 * (jt0 + j) + 2 * tig;
            *(float2*)(op0 + m) = make_float2(acc[si][j].x * z0, acc[si][j].y * z0);
            *(float2*)(op1 + m) = make_float2(acc[si][j].z * z1, acc[si][j].w * z1);
        }
    }
}

extern "C" void kernel_launch(void* const* d_in, const int* in_sizes, int n_in,
                              void* d_out, int out_size) {
    const float* Q = (const float*)d_in[0];
    const float* K = (const float*)d_in[1];
    const float* V = (const float*)d_in[2];
    float* out = (float*)d_out;

    pass1_kernel<<<dim3(SEG, Hq, Bq), 128>>>(K, V);
    reduce_kernel<<<512, 256>>>();
    pass2_kernel<<<dim3(64, Hq, Bq), 128>>>(Q, out);
}